// round 1
// baseline (speedup 1.0000x reference)
#include <cuda_runtime.h>
#include <cstdint>
#include <cstddef>

// ---------------- problem dimensions ----------------
static constexpr int N_NODES = 16384;
static constexpr int NE      = 131072;
static constexpr int NE_RO   = 32768;
static constexpr int D       = 1024;
static constexpr int DL      = 300;
static constexpr int DS      = 16;
static constexpr int NC      = 117;

// ---------------- scratch layout (floats) ----------------
static constexpr size_t SZ_ND   = (size_t)N_NODES * D;    // 16777216
static constexpr size_t SZ_NDL  = (size_t)N_NODES * DL;   // 4915200
static constexpr size_t SZ_NC   = (size_t)N_NODES * NC;   // 1916928

static constexpr size_t OFF_P1   = 0;
static constexpr size_t OFF_P2   = OFF_P1  + SZ_ND;
static constexpr size_t OFF_NF   = OFF_P2  + SZ_ND;
static constexpr size_t OFF_Q1   = OFF_NF  + SZ_ND;
static constexpr size_t OFF_Q2   = OFF_Q1  + SZ_NDL;
static constexpr size_t OFF_NFL  = OFF_Q2  + SZ_NDL;
static constexpr size_t OFF_RD   = OFF_NFL + SZ_NDL;
static constexpr size_t OFF_RS   = OFF_RD  + SZ_NC;
// zeroed region (contiguous): agg, aggl, cnt
static constexpr size_t OFF_AGG  = OFF_RS  + SZ_NC;
static constexpr size_t OFF_AGGL = OFF_AGG + SZ_ND;
static constexpr size_t OFF_CNT  = OFF_AGGL + SZ_NDL;
static constexpr size_t TOTAL_SCRATCH = OFF_CNT + N_NODES;
static constexpr size_t ZERO_FLOATS = SZ_ND + SZ_NDL + (size_t)N_NODES;

__device__ float g_scratch[TOTAL_SCRATCH];

// ---------------- zero kernel ----------------
__global__ void zero_kernel(float4* __restrict__ p, size_t n4) {
    size_t i = (size_t)blockIdx.x * blockDim.x + threadIdx.x;
    size_t stride = (size_t)gridDim.x * blockDim.x;
    float4 z = make_float4(0.f, 0.f, 0.f, 0.f);
    for (; i < n4; i += stride) p[i] = z;
}

// ---------------- generic fp32 GEMM with virtual K-concat ----------------
// C[M,Nn] = relu?( [A1 | A2] @ B + bias ), A1:[M,K1], A2:[M,K2], B:[K1+K2, Nn] (row stride ldb)
// BM=BN=128, BK=16, 256 threads, 8x8 per thread. Requires K1, K2 multiples of 4.
__global__ __launch_bounds__(256)
void gemm_cat2(const float* __restrict__ A1, int K1,
               const float* __restrict__ A2, int K2,
               const float* __restrict__ B, int ldb,
               const float* __restrict__ bias,
               float* __restrict__ Cmat, int M, int Nn, int doRelu)
{
    const int K = K1 + K2;
    __shared__ float As[16][128];
    __shared__ float Bs[16][128];

    const int tid = threadIdx.x;
    const int tx = tid & 15;
    const int ty = tid >> 4;
    const int m0 = blockIdx.y * 128;
    const int n0 = blockIdx.x * 128;

    float acc[8][8];
#pragma unroll
    for (int i = 0; i < 8; i++)
#pragma unroll
        for (int j = 0; j < 8; j++) acc[i][j] = 0.f;

    for (int k0 = 0; k0 < K; k0 += 16) {
        // load A tile: 512 float4, 2 per thread (cat boundary is 4-aligned)
#pragma unroll
        for (int t = 0; t < 2; t++) {
            int idx = tid + t * 256;
            int row = idx >> 2;
            int kl  = (idx & 3) << 2;
            int kb  = k0 + kl;
            int m   = m0 + row;
            float4 v = make_float4(0.f, 0.f, 0.f, 0.f);
            if (m < M) {
                if (kb < K1) {
                    v = *(const float4*)(A1 + (size_t)m * K1 + kb);
                } else if (kb < K) {
                    v = *(const float4*)(A2 + (size_t)m * K2 + (kb - K1));
                }
            }
            As[kl + 0][row] = v.x;
            As[kl + 1][row] = v.y;
            As[kl + 2][row] = v.z;
            As[kl + 3][row] = v.w;
        }
        // load B tile: 2048 scalars, 8 per thread, coalesced along n
#pragma unroll
        for (int t = 0; t < 8; t++) {
            int idx = tid + t * 256;
            int r   = idx >> 7;       // 0..15
            int col = idx & 127;
            int kg  = k0 + r;
            int n   = n0 + col;
            float v = 0.f;
            if (kg < K && n < Nn) v = B[(size_t)kg * ldb + n];
            Bs[r][col] = v;
        }
        __syncthreads();

#pragma unroll
        for (int kk = 0; kk < 16; kk++) {
            float a[8], b[8];
            float4 a0 = *(const float4*)&As[kk][ty * 8];
            float4 a1 = *(const float4*)&As[kk][ty * 8 + 4];
            float4 b0 = *(const float4*)&Bs[kk][tx * 8];
            float4 b1 = *(const float4*)&Bs[kk][tx * 8 + 4];
            a[0] = a0.x; a[1] = a0.y; a[2] = a0.z; a[3] = a0.w;
            a[4] = a1.x; a[5] = a1.y; a[6] = a1.z; a[7] = a1.w;
            b[0] = b0.x; b[1] = b0.y; b[2] = b0.z; b[3] = b0.w;
            b[4] = b1.x; b[5] = b1.y; b[6] = b1.z; b[7] = b1.w;
#pragma unroll
            for (int i = 0; i < 8; i++)
#pragma unroll
                for (int j = 0; j < 8; j++)
                    acc[i][j] += a[i] * b[j];
        }
        __syncthreads();
    }

#pragma unroll
    for (int i = 0; i < 8; i++) {
        int m = m0 + ty * 8 + i;
        if (m >= M) continue;
#pragma unroll
        for (int j = 0; j < 8; j++) {
            int n = n0 + tx * 8 + j;
            if (n >= Nn) continue;
            float v = acc[i][j];
            if (bias) v += bias[n];
            if (doRelu) v = fmaxf(v, 0.f);
            Cmat[(size_t)m * Nn + n] = v;
        }
    }
}

// ---------------- appearance edge combine + scatter ----------------
// m[e] = relu(P1[src] + P2[dst] + s_f[e] @ We_s + b_e); agg[dst] += m; cnt[dst] += 1
__global__ __launch_bounds__(256)
void edge_app_kernel(const float* __restrict__ P1, const float* __restrict__ P2,
                     const float* __restrict__ W_e, const float* __restrict__ b_e,
                     const float* __restrict__ s_f,
                     const int* __restrict__ esrc, const int* __restrict__ edst,
                     float* __restrict__ agg, float* __restrict__ cnt)
{
    int e = blockIdx.x;
    int s = esrc[e];
    int d = edst[e];
    __shared__ float sf[DS];
    if (threadIdx.x < DS) sf[threadIdx.x] = s_f[(size_t)e * DS + threadIdx.x];
    if (threadIdx.x == 0) atomicAdd(&cnt[d], 1.0f);
    __syncthreads();

    int c4 = threadIdx.x;  // column group: cols c4*4 .. c4*4+3
    float4 a  = ((const float4*)(P1 + (size_t)s * D))[c4];
    float4 b  = ((const float4*)(P2 + (size_t)d * D))[c4];
    float4 bb = ((const float4*)b_e)[c4];
    float acc0 = a.x + b.x + bb.x;
    float acc1 = a.y + b.y + bb.y;
    float acc2 = a.z + b.z + bb.z;
    float acc3 = a.w + b.w + bb.w;

    const float* Ws = W_e + (size_t)(2 * D) * D;  // rows 2048..2063
#pragma unroll
    for (int k = 0; k < DS; k++) {
        float f = sf[k];
        float4 w = *(const float4*)(Ws + (size_t)k * D + c4 * 4);
        acc0 += f * w.x; acc1 += f * w.y; acc2 += f * w.z; acc3 += f * w.w;
    }
    acc0 = fmaxf(acc0, 0.f); acc1 = fmaxf(acc1, 0.f);
    acc2 = fmaxf(acc2, 0.f); acc3 = fmaxf(acc3, 0.f);

    float* o = agg + (size_t)d * D + c4 * 4;
    atomicAdd(o + 0, acc0);
    atomicAdd(o + 1, acc1);
    atomicAdd(o + 2, acc2);
    atomicAdd(o + 3, acc3);
}

// ---------------- language edge combine + scatter ----------------
__global__ __launch_bounds__(96)
void edge_lang_kernel(const float* __restrict__ Q1, const float* __restrict__ Q2,
                      const float* __restrict__ b_el,
                      const int* __restrict__ esrc, const int* __restrict__ edst,
                      float* __restrict__ aggl)
{
    int e = blockIdx.x;
    int c4 = threadIdx.x;
    if (c4 >= DL / 4) return;   // 75 active
    int s = esrc[e];
    int d = edst[e];
    float4 a  = ((const float4*)(Q1 + (size_t)s * DL))[c4];
    float4 b  = ((const float4*)(Q2 + (size_t)d * DL))[c4];
    float4 bb = ((const float4*)b_el)[c4];
    float v0 = fmaxf(a.x + b.x + bb.x, 0.f);
    float v1 = fmaxf(a.y + b.y + bb.y, 0.f);
    float v2 = fmaxf(a.z + b.z + bb.z, 0.f);
    float v3 = fmaxf(a.w + b.w + bb.w, 0.f);
    float* o = aggl + (size_t)d * DL + c4 * 4;
    atomicAdd(o + 0, v0);
    atomicAdd(o + 1, v1);
    atomicAdd(o + 2, v2);
    atomicAdd(o + 3, v3);
}

// ---------------- mean-normalize both aggregates ----------------
__global__ __launch_bounds__(256)
void normalize_kernel(float* __restrict__ agg, float* __restrict__ aggl,
                      const float* __restrict__ cnt)
{
    int n = blockIdx.x;
    float inv = 1.0f / fmaxf(cnt[n], 1.0f);
    int t = threadIdx.x;
    float4* a = (float4*)(agg + (size_t)n * D);
    float4 v = a[t];
    v.x *= inv; v.y *= inv; v.z *= inv; v.w *= inv;
    a[t] = v;
    if (t < DL / 4) {
        float4* al = (float4*)(aggl + (size_t)n * DL);
        float4 w = al[t];
        w.x *= inv; w.y *= inv; w.z *= inv; w.w *= inv;
        al[t] = w;
    }
}

// ---------------- readout: pred = Rd[dst] + Rs[src] + s_f_ro @ Wp3 + b_p ----------------
__global__ __launch_bounds__(128)
void readout_kernel(const float* __restrict__ Rd, const float* __restrict__ Rs,
                    const float* __restrict__ W_p, const float* __restrict__ b_p,
                    const float* __restrict__ s_f_ro,
                    const int* __restrict__ rsrc, const int* __restrict__ rdst,
                    float* __restrict__ pred)
{
    int e = blockIdx.x;
    __shared__ float sf[DS];
    if (threadIdx.x < DS) sf[threadIdx.x] = s_f_ro[(size_t)e * DS + threadIdx.x];
    __syncthreads();
    int c = threadIdx.x;
    if (c >= NC) return;
    int s = rsrc[e];
    int d = rdst[e];
    float acc = Rd[(size_t)d * NC + c] + Rs[(size_t)s * NC + c] + b_p[c];
    const float* Wp3 = W_p + (size_t)(D + DL) * NC;  // rows 1324..1339
#pragma unroll
    for (int k = 0; k < DS; k++)
        acc += sf[k] * Wp3[(size_t)k * NC + c];
    pred[(size_t)e * NC + c] = acc;
}

// ---------------- host launcher ----------------
extern "C" void kernel_launch(void* const* d_in, const int* in_sizes, int n_in,
                              void* d_out, int out_size)
{
    const float* feat   = (const float*)d_in[0];
    const float* w2v    = (const float*)d_in[1];
    const float* s_f    = (const float*)d_in[2];
    const float* s_f_ro = (const float*)d_in[3];
    const float* W_e    = (const float*)d_in[4];
    const float* b_e    = (const float*)d_in[5];
    const float* W_el   = (const float*)d_in[6];
    const float* b_el   = (const float*)d_in[7];
    const float* W_nu   = (const float*)d_in[8];
    const float* b_nu   = (const float*)d_in[9];
    const float* W_nul  = (const float*)d_in[10];
    const float* b_nul  = (const float*)d_in[11];
    const float* W_p    = (const float*)d_in[12];
    const float* b_p    = (const float*)d_in[13];
    const int* esrc = (const int*)d_in[14];
    const int* edst = (const int*)d_in[15];
    const int* rsrc = (const int*)d_in[16];
    const int* rdst = (const int*)d_in[17];
    float* pred = (float*)d_out;

    float* sc = nullptr;
    cudaGetSymbolAddress((void**)&sc, g_scratch);
    float* P1   = sc + OFF_P1;
    float* P2   = sc + OFF_P2;
    float* NF   = sc + OFF_NF;
    float* Q1   = sc + OFF_Q1;
    float* Q2   = sc + OFF_Q2;
    float* NFL  = sc + OFF_NFL;
    float* RD   = sc + OFF_RD;
    float* RS   = sc + OFF_RS;
    float* AGG  = sc + OFF_AGG;
    float* AGGL = sc + OFF_AGGL;
    float* CNT  = sc + OFF_CNT;

    // zero agg / aggl / cnt (contiguous region)
    zero_kernel<<<4096, 256>>>((float4*)AGG, ZERO_FLOATS / 4);

    dim3 blk(256);
    dim3 grid_D((D + 127) / 128, N_NODES / 128);      // (8, 128)
    dim3 grid_DL((DL + 127) / 128, N_NODES / 128);    // (3, 128)
    dim3 grid_C((NC + 127) / 128, N_NODES / 128);     // (1, 128)

    // node-level pre-projections (appearance + language)
    gemm_cat2<<<grid_D, blk>>>(feat, D, nullptr, 0, W_e,             D,  nullptr, P1, N_NODES, D, 0);
    gemm_cat2<<<grid_D, blk>>>(feat, D, nullptr, 0, W_e + (size_t)D * D, D, nullptr, P2, N_NODES, D, 0);
    gemm_cat2<<<grid_DL, blk>>>(w2v, DL, nullptr, 0, W_el,               DL, nullptr, Q1, N_NODES, DL, 0);
    gemm_cat2<<<grid_DL, blk>>>(w2v, DL, nullptr, 0, W_el + (size_t)DL * DL, DL, nullptr, Q2, N_NODES, DL, 0);

    // edge message + scatter-mean aggregation
    edge_app_kernel<<<NE, 256>>>(P1, P2, W_e, b_e, s_f, esrc, edst, AGG, CNT);
    edge_lang_kernel<<<NE, 96>>>(Q1, Q2, b_el, esrc, edst, AGGL);
    normalize_kernel<<<N_NODES, 256>>>(AGG, AGGL, CNT);

    // node updates (concat -> virtual cat2 GEMM)
    gemm_cat2<<<grid_D, blk>>>(feat, D, AGG, D, W_nu, D, b_nu, NF, N_NODES, D, 1);
    gemm_cat2<<<grid_DL, blk>>>(w2v, DL, AGGL, DL, W_nul, DL, b_nul, NFL, N_NODES, DL, 1);

    // predictor node-level pre-projections:
    //   RD = [NF | NFL] @ W_p[0:1324)        (dst part)
    //   RS = [NFL | NF] @ W_p[1340:2664)     (src part)
    gemm_cat2<<<grid_C, blk>>>(NF, D, NFL, DL, W_p, NC, nullptr, RD, N_NODES, NC, 0);
    gemm_cat2<<<grid_C, blk>>>(NFL, DL, NF, D, W_p + (size_t)(D + DL + DS) * NC, NC, nullptr, RS, N_NODES, NC, 0);

    // final edge readout
    readout_kernel<<<NE_RO, 128>>>(RD, RS, W_p, b_p, s_f_ro, rsrc, rdst, pred);
}

// round 3
// speedup vs baseline: 4.6158x; 4.6158x over previous
#include <cuda_runtime.h>
#include <cstdint>
#include <cstddef>

// ---------------- problem dimensions ----------------
static constexpr int N_NODES = 16384;
static constexpr int NE      = 131072;
static constexpr int NE_RO   = 32768;
static constexpr int D       = 1024;
static constexpr int DL      = 300;
static constexpr int DS      = 16;
static constexpr int NC      = 117;

// ---------------- scratch layout (floats) ----------------
static constexpr size_t SZ_ND   = (size_t)N_NODES * D;
static constexpr size_t SZ_NDL  = (size_t)N_NODES * DL;
static constexpr size_t SZ_NC   = (size_t)N_NODES * NC;

static constexpr size_t OFF_P1   = 0;
static constexpr size_t OFF_P2   = OFF_P1  + SZ_ND;
static constexpr size_t OFF_NF   = OFF_P2  + SZ_ND;
static constexpr size_t OFF_Q1   = OFF_NF  + SZ_ND;
static constexpr size_t OFF_Q2   = OFF_Q1  + SZ_NDL;
static constexpr size_t OFF_NFL  = OFF_Q2  + SZ_NDL;
static constexpr size_t OFF_RD   = OFF_NFL + SZ_NDL;
static constexpr size_t OFF_RS   = OFF_RD  + SZ_NC;
static constexpr size_t OFF_AGG  = OFF_RS  + SZ_NC;
static constexpr size_t OFF_AGGL = OFF_AGG + SZ_ND;
static constexpr size_t OFF_CNT  = OFF_AGGL + SZ_NDL;
static constexpr size_t TOTAL_SCRATCH = OFF_CNT + N_NODES;
static constexpr size_t ZERO_FLOATS = SZ_ND + SZ_NDL + (size_t)N_NODES;

__device__ float g_scratch[TOTAL_SCRATCH];

// ---------------- zero kernel ----------------
__global__ void zero_kernel(float4* __restrict__ p, size_t n4) {
    size_t i = (size_t)blockIdx.x * blockDim.x + threadIdx.x;
    size_t stride = (size_t)gridDim.x * blockDim.x;
    float4 z = make_float4(0.f, 0.f, 0.f, 0.f);
    for (; i < n4; i += stride) p[i] = z;
}

// ---------------- bf16 split + mma helpers ----------------
__device__ __forceinline__ void bf16_split(float f0, float f1, uint32_t& hi, uint32_t& lo) {
    uint32_t h;
    asm("cvt.rn.satfinite.bf16x2.f32 %0, %1, %2;" : "=r"(h) : "f"(f1), "f"(f0));
    float h0 = __uint_as_float(h << 16);
    float h1 = __uint_as_float(h & 0xFFFF0000u);
    float r0 = f0 - h0;
    float r1 = f1 - h1;
    uint32_t l;
    asm("cvt.rn.satfinite.bf16x2.f32 %0, %1, %2;" : "=r"(l) : "f"(r1), "f"(r0));
    hi = h; lo = l;
}

__device__ __forceinline__ void mma_bf16(float* c, const uint32_t* a, const uint32_t* b) {
    asm volatile("mma.sync.aligned.m16n8k16.row.col.f32.bf16.bf16.f32 "
        "{%0,%1,%2,%3}, {%4,%5,%6,%7}, {%8,%9}, {%0,%1,%2,%3};"
        : "+f"(c[0]), "+f"(c[1]), "+f"(c[2]), "+f"(c[3])
        : "r"(a[0]), "r"(a[1]), "r"(a[2]), "r"(a[3]), "r"(b[0]), "r"(b[1]));
}

// ---------------- bf16x3 tensor-core GEMM with virtual K-concat ----------------
// C[M,Nn] = act( [A1 | A2] @ B + bias ), B row-major [K1+K2, ldb].
// CTA tile 128x128, K-tile 32, 8 warps (warp tile 32x64), double-buffered SMEM.
// SMEM: A fp32 [128][40] (pad), B fp32 [32][132] (pad). bf16 hi/lo split in regs.
static constexpr int A_PAD   = 40;             // floats per A row
static constexpr int B_PAD   = 132;            // floats per B row
static constexpr int A_FLTS  = 128 * A_PAD;    // 5120
static constexpr int B_FLTS  = 32 * B_PAD;     // 4224
static constexpr int BUF_FLTS = A_FLTS + B_FLTS;   // 9344
static constexpr int GM_SMEM  = 2 * BUF_FLTS * 4;  // 74752 bytes

__global__ __launch_bounds__(256)
void gemm_mma(const float* __restrict__ A1, int K1,
              const float* __restrict__ A2, int K2,
              const float* __restrict__ B, int ldb,
              const float* __restrict__ bias,
              float* __restrict__ Cmat, int Nn, int doRelu)
{
    extern __shared__ float sm[];
    const int tid  = threadIdx.x;
    const int wid  = tid >> 5;
    const int lane = tid & 31;
    const int g    = lane >> 2;
    const int t    = lane & 3;
    const int m0   = blockIdx.y * 128;
    const int n0   = blockIdx.x * 128;
    const int K    = K1 + K2;
    const int nT   = (K + 31) / 32;
    const int wm   = wid & 3;     // warp row block (32 rows)
    const int wn   = wid >> 2;    // warp col block (64 cols)
    const bool b_vec = ((ldb & 3) == 0);

    float acc[2][8][4];
#pragma unroll
    for (int i = 0; i < 2; i++)
#pragma unroll
        for (int j = 0; j < 8; j++)
#pragma unroll
            for (int k = 0; k < 4; k++) acc[i][j][k] = 0.f;

    float4 sa[4], sb[4];

    // ---- stage tile tt into registers ----
    auto load_tile = [&](int tt) {
        const int k0 = tt * 32;
#pragma unroll
        for (int i = 0; i < 4; i++) {
            int idx = i * 256 + tid;
            int row = idx >> 3, c4 = idx & 7;
            int kb = k0 + c4 * 4;
            int m  = m0 + row;
            float4 v = make_float4(0.f, 0.f, 0.f, 0.f);
            if (kb < K1)      v = *(const float4*)(A1 + (size_t)m * K1 + kb);
            else if (kb < K)  v = *(const float4*)(A2 + (size_t)m * K2 + (kb - K1));
            sa[i] = v;
        }
#pragma unroll
        for (int i = 0; i < 4; i++) {
            int idx = i * 256 + tid;
            int k = idx >> 5, n4 = idx & 31;
            int kg = k0 + k;
            int nb4 = n0 + n4 * 4;
            float4 v = make_float4(0.f, 0.f, 0.f, 0.f);
            if (kg < K) {
                const float* br = B + (size_t)kg * ldb;
                if (b_vec && nb4 + 3 < Nn) {
                    v = *(const float4*)(br + nb4);
                } else {
                    if (nb4     < Nn) v.x = br[nb4];
                    if (nb4 + 1 < Nn) v.y = br[nb4 + 1];
                    if (nb4 + 2 < Nn) v.z = br[nb4 + 2];
                    if (nb4 + 3 < Nn) v.w = br[nb4 + 3];
                }
            }
            sb[i] = v;
        }
    };

    // ---- commit staged regs to smem buffer ----
    auto store_tile = [&](int buf) {
        float* As = sm + buf * BUF_FLTS;
        float* Bs = As + A_FLTS;
#pragma unroll
        for (int i = 0; i < 4; i++) {
            int idx = i * 256 + tid;
            int row = idx >> 3, c4 = idx & 7;
            *(float4*)(As + row * A_PAD + c4 * 4) = sa[i];
        }
#pragma unroll
        for (int i = 0; i < 4; i++) {
            int idx = i * 256 + tid;
            int k = idx >> 5, n4 = idx & 31;
            *(float4*)(Bs + k * B_PAD + n4 * 4) = sb[i];
        }
    };

    // ---- compute on smem buffer ----
    auto compute = [&](int buf) {
        const float* As = sm + buf * BUF_FLTS + (wm * 32) * A_PAD;
        const float* Bs = sm + buf * BUF_FLTS + A_FLTS + wn * 64;
#pragma unroll
        for (int ks = 0; ks < 2; ks++) {
            uint32_t ahi[2][4], alo[2][4];
#pragma unroll
            for (int mb = 0; mb < 2; mb++) {
#pragma unroll
                for (int r = 0; r < 4; r++) {
                    int rowq = mb * 16 + g + (r & 1) * 8;
                    int kq   = ks * 16 + t * 2 + (r >> 1) * 8;
                    float2 f = *(const float2*)(As + rowq * A_PAD + kq);
                    bf16_split(f.x, f.y, ahi[mb][r], alo[mb][r]);
                }
            }
            uint32_t bhi[8][2], blo[8][2];
#pragma unroll
            for (int nb = 0; nb < 8; nb++) {
#pragma unroll
                for (int r = 0; r < 2; r++) {
                    int kq = ks * 16 + t * 2 + r * 8;
                    float f0 = Bs[kq * B_PAD + nb * 8 + g];
                    float f1 = Bs[(kq + 1) * B_PAD + nb * 8 + g];
                    bf16_split(f0, f1, bhi[nb][r], blo[nb][r]);
                }
            }
#pragma unroll
            for (int mb = 0; mb < 2; mb++) {
#pragma unroll
                for (int nb = 0; nb < 8; nb++) {
                    mma_bf16(acc[mb][nb], ahi[mb], bhi[nb]);
                    mma_bf16(acc[mb][nb], ahi[mb], blo[nb]);
                    mma_bf16(acc[mb][nb], alo[mb], bhi[nb]);
                }
            }
        }
    };

    // ---- pipelined main loop ----
    load_tile(0);
    store_tile(0);
    __syncthreads();
    for (int tt = 0; tt < nT; tt++) {
        if (tt + 1 < nT) load_tile(tt + 1);
        compute(tt & 1);
        if (tt + 1 < nT) {
            store_tile((tt + 1) & 1);
        }
        __syncthreads();
    }

    // ---- epilogue ----
#pragma unroll
    for (int mb = 0; mb < 2; mb++) {
#pragma unroll
        for (int nb = 0; nb < 8; nb++) {
            int n = n0 + wn * 64 + nb * 8 + t * 2;
            float bv0 = 0.f, bv1 = 0.f;
            if (bias) {
                if (n     < Nn) bv0 = bias[n];
                if (n + 1 < Nn) bv1 = bias[n + 1];
            }
#pragma unroll
            for (int h = 0; h < 2; h++) {   // h=0 -> rows g, h=1 -> rows g+8
                int m = m0 + wm * 32 + mb * 16 + g + h * 8;
                float v0 = acc[mb][nb][h * 2 + 0] + bv0;
                float v1 = acc[mb][nb][h * 2 + 1] + bv1;
                if (doRelu) { v0 = fmaxf(v0, 0.f); v1 = fmaxf(v1, 0.f); }
                float* cp = Cmat + (size_t)m * Nn + n;
                if ((Nn & 1) == 0) {
                    if (n + 1 < Nn) *(float2*)cp = make_float2(v0, v1);
                    else if (n < Nn) cp[0] = v0;
                } else {
                    if (n     < Nn) cp[0] = v0;
                    if (n + 1 < Nn) cp[1] = v1;
                }
            }
        }
    }
}

// ---------------- appearance edge combine + scatter ----------------
__global__ __launch_bounds__(256)
void edge_app_kernel(const float* __restrict__ P1, const float* __restrict__ P2,
                     const float* __restrict__ W_e, const float* __restrict__ b_e,
                     const float* __restrict__ s_f,
                     const int* __restrict__ esrc, const int* __restrict__ edst,
                     float* __restrict__ agg, float* __restrict__ cnt)
{
    int e = blockIdx.x;
    int s = esrc[e];
    int d = edst[e];
    __shared__ float sf[DS];
    if (threadIdx.x < DS) sf[threadIdx.x] = s_f[(size_t)e * DS + threadIdx.x];
    if (threadIdx.x == 0) atomicAdd(&cnt[d], 1.0f);
    __syncthreads();

    int c4 = threadIdx.x;
    float4 a  = ((const float4*)(P1 + (size_t)s * D))[c4];
    float4 b  = ((const float4*)(P2 + (size_t)d * D))[c4];
    float4 bb = ((const float4*)b_e)[c4];
    float acc0 = a.x + b.x + bb.x;
    float acc1 = a.y + b.y + bb.y;
    float acc2 = a.z + b.z + bb.z;
    float acc3 = a.w + b.w + bb.w;

    const float* Ws = W_e + (size_t)(2 * D) * D;
#pragma unroll
    for (int k = 0; k < DS; k++) {
        float f = sf[k];
        float4 w = *(const float4*)(Ws + (size_t)k * D + c4 * 4);
        acc0 += f * w.x; acc1 += f * w.y; acc2 += f * w.z; acc3 += f * w.w;
    }
    acc0 = fmaxf(acc0, 0.f); acc1 = fmaxf(acc1, 0.f);
    acc2 = fmaxf(acc2, 0.f); acc3 = fmaxf(acc3, 0.f);

    float* o = agg + (size_t)d * D + c4 * 4;
    atomicAdd(o + 0, acc0);
    atomicAdd(o + 1, acc1);
    atomicAdd(o + 2, acc2);
    atomicAdd(o + 3, acc3);
}

// ---------------- language edge combine + scatter ----------------
__global__ __launch_bounds__(96)
void edge_lang_kernel(const float* __restrict__ Q1, const float* __restrict__ Q2,
                      const float* __restrict__ b_el,
                      const int* __restrict__ esrc, const int* __restrict__ edst,
                      float* __restrict__ aggl)
{
    int e = blockIdx.x;
    int c4 = threadIdx.x;
    if (c4 >= DL / 4) return;
    int s = esrc[e];
    int d = edst[e];
    float4 a  = ((const float4*)(Q1 + (size_t)s * DL))[c4];
    float4 b  = ((const float4*)(Q2 + (size_t)d * DL))[c4];
    float4 bb = ((const float4*)b_el)[c4];
    float v0 = fmaxf(a.x + b.x + bb.x, 0.f);
    float v1 = fmaxf(a.y + b.y + bb.y, 0.f);
    float v2 = fmaxf(a.z + b.z + bb.z, 0.f);
    float v3 = fmaxf(a.w + b.w + bb.w, 0.f);
    float* o = aggl + (size_t)d * DL + c4 * 4;
    atomicAdd(o + 0, v0);
    atomicAdd(o + 1, v1);
    atomicAdd(o + 2, v2);
    atomicAdd(o + 3, v3);
}

// ---------------- mean-normalize both aggregates ----------------
__global__ __launch_bounds__(256)
void normalize_kernel(float* __restrict__ agg, float* __restrict__ aggl,
                      const float* __restrict__ cnt)
{
    int n = blockIdx.x;
    float inv = 1.0f / fmaxf(cnt[n], 1.0f);
    int t = threadIdx.x;
    float4* a = (float4*)(agg + (size_t)n * D);
    float4 v = a[t];
    v.x *= inv; v.y *= inv; v.z *= inv; v.w *= inv;
    a[t] = v;
    if (t < DL / 4) {
        float4* al = (float4*)(aggl + (size_t)n * DL);
        float4 w = al[t];
        w.x *= inv; w.y *= inv; w.z *= inv; w.w *= inv;
        al[t] = w;
    }
}

// ---------------- readout ----------------
__global__ __launch_bounds__(128)
void readout_kernel(const float* __restrict__ Rd, const float* __restrict__ Rs,
                    const float* __restrict__ W_p, const float* __restrict__ b_p,
                    const float* __restrict__ s_f_ro,
                    const int* __restrict__ rsrc, const int* __restrict__ rdst,
                    float* __restrict__ pred)
{
    int e = blockIdx.x;
    __shared__ float sf[DS];
    if (threadIdx.x < DS) sf[threadIdx.x] = s_f_ro[(size_t)e * DS + threadIdx.x];
    __syncthreads();
    int c = threadIdx.x;
    if (c >= NC) return;
    int s = rsrc[e];
    int d = rdst[e];
    float acc = Rd[(size_t)d * NC + c] + Rs[(size_t)s * NC + c] + b_p[c];
    const float* Wp3 = W_p + (size_t)(D + DL) * NC;
#pragma unroll
    for (int k = 0; k < DS; k++)
        acc += sf[k] * Wp3[(size_t)k * NC + c];
    pred[(size_t)e * NC + c] = acc;
}

// ---------------- host launcher ----------------
extern "C" void kernel_launch(void* const* d_in, const int* in_sizes, int n_in,
                              void* d_out, int out_size)
{
    const float* feat   = (const float*)d_in[0];
    const float* w2v    = (const float*)d_in[1];
    const float* s_f    = (const float*)d_in[2];
    const float* s_f_ro = (const float*)d_in[3];
    const float* W_e    = (const float*)d_in[4];
    const float* b_e    = (const float*)d_in[5];
    const float* W_el   = (const float*)d_in[6];
    const float* b_el   = (const float*)d_in[7];
    const float* W_nu   = (const float*)d_in[8];
    const float* b_nu   = (const float*)d_in[9];
    const float* W_nul  = (const float*)d_in[10];
    const float* b_nul  = (const float*)d_in[11];
    const float* W_p    = (const float*)d_in[12];
    const float* b_p    = (const float*)d_in[13];
    const int* esrc = (const int*)d_in[14];
    const int* edst = (const int*)d_in[15];
    const int* rsrc = (const int*)d_in[16];
    const int* rdst = (const int*)d_in[17];
    float* pred = (float*)d_out;

    float* sc = nullptr;
    cudaGetSymbolAddress((void**)&sc, g_scratch);
    float* P1   = sc + OFF_P1;
    float* P2   = sc + OFF_P2;
    float* NF   = sc + OFF_NF;
    float* Q1   = sc + OFF_Q1;
    float* Q2   = sc + OFF_Q2;
    float* NFL  = sc + OFF_NFL;
    float* RD   = sc + OFF_RD;
    float* RS   = sc + OFF_RS;
    float* AGG  = sc + OFF_AGG;
    float* AGGL = sc + OFF_AGGL;
    float* CNT  = sc + OFF_CNT;

    cudaFuncSetAttribute(gemm_mma, cudaFuncAttributeMaxDynamicSharedMemorySize, GM_SMEM);

    zero_kernel<<<4096, 256>>>((float4*)AGG, ZERO_FLOATS / 4);

    dim3 blk(256);
    dim3 grid_D(8, 128);    // Nn=1024
    dim3 grid_DL(3, 128);   // Nn=300
    dim3 grid_C(1, 128);    // Nn=117

    // node-level pre-projections
    gemm_mma<<<grid_D,  blk, GM_SMEM>>>(feat, D, nullptr, 0, W_e,                    D,  nullptr, P1, D,  0);
    gemm_mma<<<grid_D,  blk, GM_SMEM>>>(feat, D, nullptr, 0, W_e + (size_t)D * D,    D,  nullptr, P2, D,  0);
    gemm_mma<<<grid_DL, blk, GM_SMEM>>>(w2v, DL, nullptr, 0, W_el,                   DL, nullptr, Q1, DL, 0);
    gemm_mma<<<grid_DL, blk, GM_SMEM>>>(w2v, DL, nullptr, 0, W_el + (size_t)DL * DL, DL, nullptr, Q2, DL, 0);

    // edge message + scatter-mean aggregation
    edge_app_kernel<<<NE, 256>>>(P1, P2, W_e, b_e, s_f, esrc, edst, AGG, CNT);
    edge_lang_kernel<<<NE, 96>>>(Q1, Q2, b_el, esrc, edst, AGGL);
    normalize_kernel<<<N_NODES, 256>>>(AGG, AGGL, CNT);

    // node updates
    gemm_mma<<<grid_D,  blk, GM_SMEM>>>(feat, D, AGG,  D,  W_nu,  D,  b_nu,  NF,  D,  1);
    gemm_mma<<<grid_DL, blk, GM_SMEM>>>(w2v, DL, AGGL, DL, W_nul, DL, b_nul, NFL, DL, 1);

    // predictor node-level pre-projections
    gemm_mma<<<grid_C, blk, GM_SMEM>>>(NF, D, NFL, DL, W_p, NC, nullptr, RD, NC, 0);
    gemm_mma<<<grid_C, blk, GM_SMEM>>>(NFL, DL, NF, D, W_p + (size_t)(D + DL + DS) * NC, NC, nullptr, RS, NC, 0);

    // final edge readout
    readout_kernel<<<NE_RO, 128>>>(RD, RS, W_p, b_p, s_f_ro, rsrc, rdst, pred);
}